// round 7
// baseline (speedup 1.0000x reference)
#include <cuda_runtime.h>
#include <cuda_bf16.h>
#include <math_constants.h>

#define FIN 128
#define HID 64
#define NNODES 100000
#define NEDGES 1600000
#define SCAN_CHUNK 1024
#define FULLMASK 0xFFFFFFFFu

// ---------------- scratch (static device globals; no allocation) -------------
__device__ __align__(256) float g_h[NNODES * HID];
__device__ __align__(256) float g_agg[NNODES * HID];
__device__ __align__(256) float g_as[NNODES];
__device__ __align__(256) float g_ad[NNODES];
__device__ __align__(256) int g_deg1[NNODES],        g_deg2[NNODES];
__device__ __align__(256) int g_rp1[NNODES + 1],     g_rp2[NNODES + 1];
__device__ __align__(256) int g_cur1[NNODES],        g_cur2[NNODES];
__device__ __align__(256) int g_csr1[NEDGES],        g_csr2[NEDGES];
__device__ __align__(256) int g_bsum1[256],          g_bsum2[256];

// ---------------- GEMM + fused attention scores (device body) ----------------
// C[n,64] = X[n,K] @ W[K,64]; tile 128 rows x 64 cols, micro 8x4 per thread.
template <int K>
__device__ __forceinline__ void gemm_score_body(int bid,
        const float* __restrict__ X, const float* __restrict__ W,
        const float* __restrict__ att_s, const float* __restrict__ att_d,
        float* __restrict__ C, float* __restrict__ as_, float* __restrict__ ad_,
        int n) {
    __shared__ float Xs[128][36];
    __shared__ float Ws[32][64];
    int tid = threadIdx.x;
    int tx = tid & 15;
    int ty = tid >> 4;
    int row0 = bid * 128;
    float acc[8][4] = {};
    for (int k0 = 0; k0 < K; k0 += 32) {
        for (int l = tid; l < 1024; l += 256) {
            int r = l >> 3, c4 = l & 7;
            int nd = row0 + r;
            float4 v = make_float4(0.f, 0.f, 0.f, 0.f);
            if (nd < n) v = *reinterpret_cast<const float4*>(X + (size_t)nd * K + k0 + c4 * 4);
            *reinterpret_cast<float4*>(&Xs[r][c4 * 4]) = v;
        }
        for (int l = tid; l < 512; l += 256) {
            int kk = l >> 4, c4 = l & 15;
            *reinterpret_cast<float4*>(&Ws[kk][c4 * 4]) =
                *reinterpret_cast<const float4*>(W + (size_t)(k0 + kk) * 64 + c4 * 4);
        }
        __syncthreads();
#pragma unroll
        for (int kk = 0; kk < 32; kk += 4) {
            float4 wv0 = *reinterpret_cast<float4*>(&Ws[kk + 0][tx * 4]);
            float4 wv1 = *reinterpret_cast<float4*>(&Ws[kk + 1][tx * 4]);
            float4 wv2 = *reinterpret_cast<float4*>(&Ws[kk + 2][tx * 4]);
            float4 wv3 = *reinterpret_cast<float4*>(&Ws[kk + 3][tx * 4]);
#pragma unroll
            for (int r = 0; r < 8; r++) {
                float4 xq = *reinterpret_cast<float4*>(&Xs[ty * 8 + r][kk]);
                acc[r][0] += xq.x * wv0.x; acc[r][1] += xq.x * wv0.y;
                acc[r][2] += xq.x * wv0.z; acc[r][3] += xq.x * wv0.w;
                acc[r][0] += xq.y * wv1.x; acc[r][1] += xq.y * wv1.y;
                acc[r][2] += xq.y * wv1.z; acc[r][3] += xq.y * wv1.w;
                acc[r][0] += xq.z * wv2.x; acc[r][1] += xq.z * wv2.y;
                acc[r][2] += xq.z * wv2.z; acc[r][3] += xq.z * wv2.w;
                acc[r][0] += xq.w * wv3.x; acc[r][1] += xq.w * wv3.y;
                acc[r][2] += xq.w * wv3.z; acc[r][3] += xq.w * wv3.w;
            }
        }
        __syncthreads();
    }
    float asv[4], adv[4];
#pragma unroll
    for (int c = 0; c < 4; c++) { asv[c] = att_s[tx * 4 + c]; adv[c] = att_d[tx * 4 + c]; }
#pragma unroll
    for (int r = 0; r < 8; r++) {
        int nd = row0 + ty * 8 + r;
        if (nd < n)
            *reinterpret_cast<float4*>(C + (size_t)nd * 64 + tx * 4) =
                make_float4(acc[r][0], acc[r][1], acc[r][2], acc[r][3]);
        float ps = acc[r][0] * asv[0] + acc[r][1] * asv[1] + acc[r][2] * asv[2] + acc[r][3] * asv[3];
        float pd = acc[r][0] * adv[0] + acc[r][1] * adv[1] + acc[r][2] * adv[2] + acc[r][3] * adv[3];
#pragma unroll
        for (int o = 1; o < 16; o <<= 1) {
            ps += __shfl_xor_sync(FULLMASK, ps, o);
            pd += __shfl_xor_sync(FULLMASK, pd, o);
        }
        if (tx == 0 && nd < n) { as_[nd] = ps; ad_[nd] = pd; }
    }
}

// ---------------- K1: zero both degree arrays --------------------------------
__global__ void zero2_kernel(int* __restrict__ d1, int* __restrict__ d2, int n) {
    int i = blockIdx.x * blockDim.x + threadIdx.x;
    if (i < n) { d1[i] = 0; d2[i] = 0; }
}

// ---------------- K2: gemm_score layer1  ||  hist1  ||  hist2 ----------------
__global__ void gemm1_hist_kernel(const float* __restrict__ X, const float* __restrict__ W,
        const float* __restrict__ att_s, const float* __restrict__ att_d,
        float* __restrict__ C, float* __restrict__ as_, float* __restrict__ ad_, int n,
        int gemm_blocks,
        const int* __restrict__ dst1, int* __restrict__ deg1,
        const int* __restrict__ dst2, int* __restrict__ deg2, int ne, int hb) {
    int bid = blockIdx.x;
    if (bid < gemm_blocks) {
        gemm_score_body<FIN>(bid, X, W, att_s, att_d, C, as_, ad_, n);
        return;
    }
    bid -= gemm_blocks;
    const int* dstp; int* deg;
    if (bid < hb) { dstp = dst1; deg = deg1; }
    else          { bid -= hb; dstp = dst2; deg = deg2; }
    int base = (bid * blockDim.x + threadIdx.x) * 4;
    if (base + 3 < ne) {
        int4 d4 = *reinterpret_cast<const int4*>(dstp + base);
        atomicAdd(&deg[d4.x], 1);
        atomicAdd(&deg[d4.y], 1);
        atomicAdd(&deg[d4.z], 1);
        atomicAdd(&deg[d4.w], 1);
    } else {
        for (int i = base; i < ne; i++) atomicAdd(&deg[dstp[i]], 1);
    }
}

// ---------------- K3: per-chunk scan of both degree arrays -------------------
__global__ void scan_block2_kernel(const int* __restrict__ deg1, const int* __restrict__ deg2,
                                   int* __restrict__ rp1, int* __restrict__ rp2,
                                   int* __restrict__ bs1, int* __restrict__ bs2,
                                   int n, int sb) {
    __shared__ int tsum[256];
    int b = blockIdx.x;
    const int* deg; int* rowptr; int* bsum;
    if (b < sb) { deg = deg1; rowptr = rp1; bsum = bs1; }
    else        { b -= sb; deg = deg2; rowptr = rp2; bsum = bs2; }
    int t = threadIdx.x;
    int base = b * SCAN_CHUNK + t * 4;
    int v[4]; int s = 0;
#pragma unroll
    for (int j = 0; j < 4; j++) { v[j] = (base + j < n) ? deg[base + j] : 0; s += v[j]; }
    tsum[t] = s;
    __syncthreads();
    int acc = s;
    for (int off = 1; off < 256; off <<= 1) {
        int x = (t >= off) ? tsum[t - off] : 0;
        __syncthreads();
        tsum[t] += x;
        __syncthreads();
    }
    int excl = tsum[t] - acc;
    if (t == 255) bsum[b] = tsum[255];
    int run = excl;
#pragma unroll
    for (int j = 0; j < 4; j++) {
        if (base + j < n) rowptr[base + j] = run;
        run += v[j];
    }
}

// ---------------- K4: add chunk prefixes, init cur ---------------------------
__global__ void scan_add2_kernel(int* __restrict__ rp1, int* __restrict__ cur1,
                                 const int* __restrict__ bs1,
                                 int* __restrict__ rp2, int* __restrict__ cur2,
                                 const int* __restrict__ bs2,
                                 int n, int e, int node_blocks) {
    __shared__ int red[256];
    int b = blockIdx.x;
    int* rowptr; int* cur; const int* bsum;
    if (b < node_blocks) { rowptr = rp1; cur = cur1; bsum = bs1; }
    else                 { b -= node_blocks; rowptr = rp2; cur = cur2; bsum = bs2; }
    int t = threadIdx.x;
    int c = b >> 2;
    red[t] = (t < c) ? bsum[t] : 0;
    __syncthreads();
    for (int off = 128; off; off >>= 1) {
        if (t < off) red[t] += red[t + off];
        __syncthreads();
    }
    int prefix = red[0];
    int i = b * 256 + t;
    if (i < n) {
        int v = rowptr[i] + prefix;
        rowptr[i] = v;
        cur[i] = v;
    }
    if (b == 0 && t == 0) rowptr[n] = e;
}

// ---------------- K5: scatter layer 1 ----------------------------------------
__global__ void scatter1_kernel(const int* __restrict__ src, const int* __restrict__ dst,
                                int* __restrict__ cur, int* __restrict__ csr, int ne) {
    int i = blockIdx.x * blockDim.x + threadIdx.x;
    if (i >= ne) return;
    int d = dst[i];
    int p = atomicAdd(&cur[d], 1);
    csr[p] = src[i];
}

// ---------------- aggregation core: no-max softmax, MLP=8 gather batches -----
// exp(e)/sum(exp(e)) == softmax (e bounded, |e| < ~20 -> no overflow in fp32).
__device__ __forceinline__ void aggr_core(const int* __restrict__ rowptr,
                                          const int* __restrict__ csr,
                                          const float* __restrict__ as_,
                                          const float* __restrict__ ad_,
                                          const float* __restrict__ h,
                                          int nd, int lane,
                                          float& ro0, float& ro1) {
    int start = rowptr[nd];
    int end = rowptr[nd + 1];
    float adv = ad_[nd];
    float ssum = 0.f, a0 = 0.f, a1 = 0.f;
    for (int base = start; base < end; base += 32) {
        int i = base + lane;
        bool valid = (i < end);
        int s = valid ? csr[i] : 0;
        float w = 0.f;
        if (valid) {
            float v = as_[s] + adv;
            v = (v > 0.f) ? v : 0.2f * v;
            w = __expf(v);
        }
        ssum += w;                   // per-lane partial; reduced once at the end
        int cnt = min(32, end - base);
        for (int j = 0; j < cnt; j += 8) {      // lanes >= cnt carry w=0, s=0
            float wv[8]; float2 hv[8];
#pragma unroll
            for (int k = 0; k < 8; k++) {
                int sj = __shfl_sync(FULLMASK, s, j + k);
                wv[k] = __shfl_sync(FULLMASK, w, j + k);
                hv[k] = *reinterpret_cast<const float2*>(h + (size_t)sj * 64 + lane * 2);
            }
#pragma unroll
            for (int k = 0; k < 8; k++) { a0 += wv[k] * hv[k].x; a1 += wv[k] * hv[k].y; }
        }
    }
#pragma unroll
    for (int o = 16; o; o >>= 1) ssum += __shfl_xor_sync(FULLMASK, ssum, o);
    float inv = 1.f / (ssum + 1e-16f);
    ro0 = a0 * inv;
    ro1 = a1 * inv;
}

// ---------------- K6: aggr layer1 (+bias+relu)  ||  scatter layer2 -----------
__global__ void aggr_scatter_kernel(const int* __restrict__ rowptr, const int* __restrict__ csr,
        const float* __restrict__ as_, const float* __restrict__ ad_,
        const float* __restrict__ h, const float* __restrict__ bias,
        float* __restrict__ aggout, int n, int warp_blocks,
        const int* __restrict__ src2, const int* __restrict__ dst2,
        int* __restrict__ cur2, int* __restrict__ csr2, int ne) {
    int b = blockIdx.x;
    if (b >= warp_blocks) {                 // scatter for layer 2
        b -= warp_blocks;
        int i = b * blockDim.x + threadIdx.x;
        if (i < ne) {
            int d = dst2[i];
            int p = atomicAdd(&cur2[d], 1);
            csr2[p] = src2[i];
        }
        return;
    }
    int gt = b * blockDim.x + threadIdx.x;
    int nd = gt >> 5;
    int lane = gt & 31;
    if (nd >= n) return;
    float o0, o1;
    aggr_core(rowptr, csr, as_, ad_, h, nd, lane, o0, o1);
    o0 = fmaxf(o0 + bias[lane * 2], 0.f);
    o1 = fmaxf(o1 + bias[lane * 2 + 1], 0.f);
    *reinterpret_cast<float2*>(aggout + (size_t)nd * 64 + lane * 2) = make_float2(o0, o1);
}

// ---------------- K7: gemm_score layer2 --------------------------------------
__global__ void gemm2_kernel(const float* __restrict__ X, const float* __restrict__ W,
        const float* __restrict__ att_s, const float* __restrict__ att_d,
        float* __restrict__ C, float* __restrict__ as_, float* __restrict__ ad_, int n) {
    gemm_score_body<HID>(blockIdx.x, X, W, att_s, att_d, C, as_, ad_, n);
}

// ---------------- K8: aggr layer2 + bias + linear + log_softmax --------------
// 4 nodes per warp (amortizes the 8KB Wlin smem load 4x vs one-node-per-warp).
__global__ void aggr_final_kernel(const int* __restrict__ rowptr, const int* __restrict__ csr,
        const float* __restrict__ as_, const float* __restrict__ ad_,
        const float* __restrict__ h, const float* __restrict__ bias,
        const float* __restrict__ Wlin, const float* __restrict__ blin,
        float* __restrict__ out, int n, int total_warps) {
    __shared__ float Ws[64 * 32];
    for (int i = threadIdx.x; i < 64 * 32; i += blockDim.x) Ws[i] = Wlin[i];
    __syncthreads();
    int lane = threadIdx.x & 31;
    int gw = (blockIdx.x * blockDim.x + threadIdx.x) >> 5;
    float b0 = bias[2 * lane], b1v = bias[2 * lane + 1];
    float blv = blin[lane];
#pragma unroll
    for (int it = 0; it < 4; it++) {
        int nd = gw + it * total_warps;
        if (nd >= n) return;
        float o0, o1;
        aggr_core(rowptr, csr, as_, ad_, h, nd, lane, o0, o1);
        o0 += b0;
        o1 += b1v;
        float y = blv;
#pragma unroll
        for (int j = 0; j < 32; j++) {
            float r0 = __shfl_sync(FULLMASK, o0, j);
            float r1 = __shfl_sync(FULLMASK, o1, j);
            y += r0 * Ws[(2 * j) * 32 + lane] + r1 * Ws[(2 * j + 1) * 32 + lane];
        }
        float m = y;
#pragma unroll
        for (int o = 16; o; o >>= 1) m = fmaxf(m, __shfl_xor_sync(FULLMASK, m, o));
        float ex = __expf(y - m);
        float ss = ex;
#pragma unroll
        for (int o = 16; o; o >>= 1) ss += __shfl_xor_sync(FULLMASK, ss, o);
        out[(size_t)nd * 32 + lane] = y - m - __logf(ss);
    }
}

// ---------------- launch ------------------------------------------------------
extern "C" void kernel_launch(void* const* d_in, const int* in_sizes, int n_in,
                              void* d_out, int out_size) {
    const float* x        = (const float*)d_in[0];
    const int*   ei1      = (const int*)d_in[1];
    const int*   ei2      = (const int*)d_in[2];
    const float* W1       = (const float*)d_in[3];
    const float* att_src1 = (const float*)d_in[4];
    const float* att_dst1 = (const float*)d_in[5];
    const float* b1       = (const float*)d_in[6];
    const float* W2       = (const float*)d_in[7];
    const float* att_src2 = (const float*)d_in[8];
    const float* att_dst2 = (const float*)d_in[9];
    const float* b2       = (const float*)d_in[10];
    const float* Wlin     = (const float*)d_in[11];
    const float* blin     = (const float*)d_in[12];
    float* out = (float*)d_out;

    const int n = in_sizes[0] / FIN;       // 100000
    const int e = in_sizes[1] / 2;         // 1600000

    float *h, *agg, *as_, *ad_;
    int *deg1, *rp1, *cur1, *csr1, *bs1;
    int *deg2, *rp2, *cur2, *csr2, *bs2;
    cudaGetSymbolAddress((void**)&h,    g_h);
    cudaGetSymbolAddress((void**)&agg,  g_agg);
    cudaGetSymbolAddress((void**)&as_,  g_as);
    cudaGetSymbolAddress((void**)&ad_,  g_ad);
    cudaGetSymbolAddress((void**)&deg1, g_deg1);
    cudaGetSymbolAddress((void**)&rp1,  g_rp1);
    cudaGetSymbolAddress((void**)&cur1, g_cur1);
    cudaGetSymbolAddress((void**)&csr1, g_csr1);
    cudaGetSymbolAddress((void**)&bs1,  g_bsum1);
    cudaGetSymbolAddress((void**)&deg2, g_deg2);
    cudaGetSymbolAddress((void**)&rp2,  g_rp2);
    cudaGetSymbolAddress((void**)&cur2, g_cur2);
    cudaGetSymbolAddress((void**)&csr2, g_csr2);
    cudaGetSymbolAddress((void**)&bs2,  g_bsum2);

    const int TB = 256;
    int gemm_blocks = (n + 127) / 128;                   // 782
    int node_blocks = (n + TB - 1) / TB;                 // 391
    int warp_blocks = (n * 32 + TB - 1) / TB;            // 12500
    int eb          = (e + TB - 1) / TB;                 // 6250
    int hb          = (e + 4 * TB - 1) / (4 * TB);       // 1563
    int sb          = (n + SCAN_CHUNK - 1) / SCAN_CHUNK; // 98
    // K8: 4 nodes per warp
    int fin_blocks  = (warp_blocks + 3) / 4;             // 3125
    int fin_warps   = fin_blocks * 8;                    // 25000

    // K1: zero degree arrays
    zero2_kernel<<<node_blocks, TB>>>(deg1, deg2, n);
    // K2: gemm1+score1 || hist1 || hist2
    gemm1_hist_kernel<<<gemm_blocks + 2 * hb, TB>>>(
        x, W1, att_src1, att_dst1, h, as_, ad_, n, gemm_blocks,
        ei1 + e, deg1, ei2 + e, deg2, e, hb);
    // K3/K4: rowptr scans (both layers)
    scan_block2_kernel<<<2 * sb, TB>>>(deg1, deg2, rp1, rp2, bs1, bs2, n, sb);
    scan_add2_kernel<<<2 * node_blocks, TB>>>(rp1, cur1, bs1, rp2, cur2, bs2, n, e, node_blocks);
    // K5: scatter layer 1
    scatter1_kernel<<<eb, TB>>>(ei1, ei1 + e, cur1, csr1, e);
    // K6: aggr layer1 (+bias+relu)  ||  scatter layer 2
    aggr_scatter_kernel<<<warp_blocks + eb, TB>>>(
        rp1, csr1, as_, ad_, h, b1, agg, n, warp_blocks,
        ei2, ei2 + e, cur2, csr2, e);
    // K7: gemm2+score2
    gemm2_kernel<<<gemm_blocks, TB>>>(agg, W2, att_src2, att_dst2, h, as_, ad_, n);
    // K8: aggr layer2 + linear + log_softmax
    aggr_final_kernel<<<fin_blocks, TB>>>(
        rp2, csr2, as_, ad_, h, b2, Wlin, blin, out, n, fin_warps);
}

// round 8
// speedup vs baseline: 1.4543x; 1.4543x over previous
#include <cuda_runtime.h>
#include <cuda_bf16.h>
#include <math_constants.h>

#define FIN 128
#define HID 64
#define NNODES 100000
#define NEDGES 1600000
#define SCAN_CHUNK 1024
#define FULLMASK 0xFFFFFFFFu

// ---------------- scratch (static device globals; no allocation) -------------
__device__ __align__(256) float g_h[NNODES * HID];
__device__ __align__(256) float g_agg[NNODES * HID];
__device__ __align__(256) float g_as[NNODES];
__device__ __align__(256) float g_ad[NNODES];
__device__ __align__(256) int g_deg1[NNODES],        g_deg2[NNODES];
__device__ __align__(256) int g_rp1[NNODES + 1],     g_rp2[NNODES + 1];
__device__ __align__(256) int g_cur1[NNODES],        g_cur2[NNODES];
__device__ __align__(256) int g_csr1[NEDGES],        g_csr2[NEDGES];
__device__ __align__(256) int g_bsum1[256],          g_bsum2[256];

// ---------------- GEMM + fused attention scores (device body) ----------------
// C[n,64] = X[n,K] @ W[K,64]; tile 128 rows x 64 cols, micro 8x4 per thread.
template <int K>
__device__ __forceinline__ void gemm_score_body(int bid,
        const float* __restrict__ X, const float* __restrict__ W,
        const float* __restrict__ att_s, const float* __restrict__ att_d,
        float* __restrict__ C, float* __restrict__ as_, float* __restrict__ ad_,
        int n) {
    __shared__ float Xs[128][36];
    __shared__ float Ws[32][64];
    int tid = threadIdx.x;
    int tx = tid & 15;
    int ty = tid >> 4;
    int row0 = bid * 128;
    float acc[8][4] = {};
    for (int k0 = 0; k0 < K; k0 += 32) {
        for (int l = tid; l < 1024; l += 256) {
            int r = l >> 3, c4 = l & 7;
            int nd = row0 + r;
            float4 v = make_float4(0.f, 0.f, 0.f, 0.f);
            if (nd < n) v = *reinterpret_cast<const float4*>(X + (size_t)nd * K + k0 + c4 * 4);
            *reinterpret_cast<float4*>(&Xs[r][c4 * 4]) = v;
        }
        for (int l = tid; l < 512; l += 256) {
            int kk = l >> 4, c4 = l & 15;
            *reinterpret_cast<float4*>(&Ws[kk][c4 * 4]) =
                *reinterpret_cast<const float4*>(W + (size_t)(k0 + kk) * 64 + c4 * 4);
        }
        __syncthreads();
#pragma unroll
        for (int kk = 0; kk < 32; kk += 4) {
            float4 wv0 = *reinterpret_cast<float4*>(&Ws[kk + 0][tx * 4]);
            float4 wv1 = *reinterpret_cast<float4*>(&Ws[kk + 1][tx * 4]);
            float4 wv2 = *reinterpret_cast<float4*>(&Ws[kk + 2][tx * 4]);
            float4 wv3 = *reinterpret_cast<float4*>(&Ws[kk + 3][tx * 4]);
#pragma unroll
            for (int r = 0; r < 8; r++) {
                float4 xq = *reinterpret_cast<float4*>(&Xs[ty * 8 + r][kk]);
                acc[r][0] += xq.x * wv0.x; acc[r][1] += xq.x * wv0.y;
                acc[r][2] += xq.x * wv0.z; acc[r][3] += xq.x * wv0.w;
                acc[r][0] += xq.y * wv1.x; acc[r][1] += xq.y * wv1.y;
                acc[r][2] += xq.y * wv1.z; acc[r][3] += xq.y * wv1.w;
                acc[r][0] += xq.z * wv2.x; acc[r][1] += xq.z * wv2.y;
                acc[r][2] += xq.z * wv2.z; acc[r][3] += xq.z * wv2.w;
                acc[r][0] += xq.w * wv3.x; acc[r][1] += xq.w * wv3.y;
                acc[r][2] += xq.w * wv3.z; acc[r][3] += xq.w * wv3.w;
            }
        }
        __syncthreads();
    }
    float asv[4], adv[4];
#pragma unroll
    for (int c = 0; c < 4; c++) { asv[c] = att_s[tx * 4 + c]; adv[c] = att_d[tx * 4 + c]; }
#pragma unroll
    for (int r = 0; r < 8; r++) {
        int nd = row0 + ty * 8 + r;
        if (nd < n)
            *reinterpret_cast<float4*>(C + (size_t)nd * 64 + tx * 4) =
                make_float4(acc[r][0], acc[r][1], acc[r][2], acc[r][3]);
        float ps = acc[r][0] * asv[0] + acc[r][1] * asv[1] + acc[r][2] * asv[2] + acc[r][3] * asv[3];
        float pd = acc[r][0] * adv[0] + acc[r][1] * adv[1] + acc[r][2] * adv[2] + acc[r][3] * adv[3];
#pragma unroll
        for (int o = 1; o < 16; o <<= 1) {
            ps += __shfl_xor_sync(FULLMASK, ps, o);
            pd += __shfl_xor_sync(FULLMASK, pd, o);
        }
        if (tx == 0 && nd < n) { as_[nd] = ps; ad_[nd] = pd; }
    }
}

// ---------------- K1: zero both degree arrays --------------------------------
__global__ void zero2_kernel(int* __restrict__ d1, int* __restrict__ d2, int n) {
    int i = blockIdx.x * blockDim.x + threadIdx.x;
    if (i < n) { d1[i] = 0; d2[i] = 0; }
}

// ---------------- K2: gemm_score layer1  ||  hist1  ||  hist2 ----------------
__global__ void gemm1_hist_kernel(const float* __restrict__ X, const float* __restrict__ W,
        const float* __restrict__ att_s, const float* __restrict__ att_d,
        float* __restrict__ C, float* __restrict__ as_, float* __restrict__ ad_, int n,
        int gemm_blocks,
        const int* __restrict__ dst1, int* __restrict__ deg1,
        const int* __restrict__ dst2, int* __restrict__ deg2, int ne, int hb) {
    int bid = blockIdx.x;
    if (bid < gemm_blocks) {
        gemm_score_body<FIN>(bid, X, W, att_s, att_d, C, as_, ad_, n);
        return;
    }
    bid -= gemm_blocks;
    const int* dstp; int* deg;
    if (bid < hb) { dstp = dst1; deg = deg1; }
    else          { bid -= hb; dstp = dst2; deg = deg2; }
    int base = (bid * blockDim.x + threadIdx.x) * 4;
    if (base + 3 < ne) {
        int4 d4 = *reinterpret_cast<const int4*>(dstp + base);
        atomicAdd(&deg[d4.x], 1);
        atomicAdd(&deg[d4.y], 1);
        atomicAdd(&deg[d4.z], 1);
        atomicAdd(&deg[d4.w], 1);
    } else {
        for (int i = base; i < ne; i++) atomicAdd(&deg[dstp[i]], 1);
    }
}

// ---------------- K3: per-chunk scan of both degree arrays -------------------
__global__ void scan_block2_kernel(const int* __restrict__ deg1, const int* __restrict__ deg2,
                                   int* __restrict__ rp1, int* __restrict__ rp2,
                                   int* __restrict__ bs1, int* __restrict__ bs2,
                                   int n, int sb) {
    __shared__ int tsum[256];
    int b = blockIdx.x;
    const int* deg; int* rowptr; int* bsum;
    if (b < sb) { deg = deg1; rowptr = rp1; bsum = bs1; }
    else        { b -= sb; deg = deg2; rowptr = rp2; bsum = bs2; }
    int t = threadIdx.x;
    int base = b * SCAN_CHUNK + t * 4;
    int v[4]; int s = 0;
#pragma unroll
    for (int j = 0; j < 4; j++) { v[j] = (base + j < n) ? deg[base + j] : 0; s += v[j]; }
    tsum[t] = s;
    __syncthreads();
    int acc = s;
    for (int off = 1; off < 256; off <<= 1) {
        int x = (t >= off) ? tsum[t - off] : 0;
        __syncthreads();
        tsum[t] += x;
        __syncthreads();
    }
    int excl = tsum[t] - acc;
    if (t == 255) bsum[b] = tsum[255];
    int run = excl;
#pragma unroll
    for (int j = 0; j < 4; j++) {
        if (base + j < n) rowptr[base + j] = run;
        run += v[j];
    }
}

// ---------------- K4: add chunk prefixes, init cur ---------------------------
__global__ void scan_add2_kernel(int* __restrict__ rp1, int* __restrict__ cur1,
                                 const int* __restrict__ bs1,
                                 int* __restrict__ rp2, int* __restrict__ cur2,
                                 const int* __restrict__ bs2,
                                 int n, int e, int node_blocks) {
    __shared__ int red[256];
    int b = blockIdx.x;
    int* rowptr; int* cur; const int* bsum;
    if (b < node_blocks) { rowptr = rp1; cur = cur1; bsum = bs1; }
    else                 { b -= node_blocks; rowptr = rp2; cur = cur2; bsum = bs2; }
    int t = threadIdx.x;
    int c = b >> 2;
    red[t] = (t < c) ? bsum[t] : 0;
    __syncthreads();
    for (int off = 128; off; off >>= 1) {
        if (t < off) red[t] += red[t + off];
        __syncthreads();
    }
    int prefix = red[0];
    int i = b * 256 + t;
    if (i < n) {
        int v = rowptr[i] + prefix;
        rowptr[i] = v;
        cur[i] = v;
    }
    if (b == 0 && t == 0) rowptr[n] = e;
}

// ---------------- K5: scatter layer 1 (int4, 4 edges/thread) -----------------
__global__ void scatter1_kernel(const int* __restrict__ src, const int* __restrict__ dst,
                                int* __restrict__ cur, int* __restrict__ csr, int ne) {
    int base = (blockIdx.x * blockDim.x + threadIdx.x) * 4;
    if (base + 3 < ne) {
        int4 s4 = *reinterpret_cast<const int4*>(src + base);
        int4 d4 = *reinterpret_cast<const int4*>(dst + base);
        int p;
        p = atomicAdd(&cur[d4.x], 1); csr[p] = s4.x;
        p = atomicAdd(&cur[d4.y], 1); csr[p] = s4.y;
        p = atomicAdd(&cur[d4.z], 1); csr[p] = s4.z;
        p = atomicAdd(&cur[d4.w], 1); csr[p] = s4.w;
    } else {
        for (int i = base; i < ne; i++) {
            int p = atomicAdd(&cur[dst[i]], 1);
            csr[p] = src[i];
        }
    }
}

// ---------------- fused single-pass softmax + aggregation (flash-style) ------
// warp per dst node; online max with accumulator rescaling; normalize at end.
__device__ __forceinline__ void aggr_core(const int* __restrict__ rowptr,
                                          const int* __restrict__ csr,
                                          const float* __restrict__ as_,
                                          const float* __restrict__ ad_,
                                          const float* __restrict__ h,
                                          int nd, int lane,
                                          float& ro0, float& ro1) {
    int start = rowptr[nd];
    int end = rowptr[nd + 1];
    float adv = ad_[nd];
    float m = -CUDART_INF_F;
    float ssum = 0.f;
    float a0 = 0.f, a1 = 0.f;
    for (int base = start; base < end; base += 32) {
        int i = base + lane;
        bool valid = (i < end);
        int s = valid ? csr[i] : 0;
        float e = -CUDART_INF_F;
        if (valid) {
            float v = as_[s] + adv;
            e = (v > 0.f) ? v : 0.2f * v;
        }
        float cm = e;
#pragma unroll
        for (int o = 16; o; o >>= 1) cm = fmaxf(cm, __shfl_xor_sync(FULLMASK, cm, o));
        float mnew = fmaxf(m, cm);
        float scale = __expf(m - mnew);
        ssum *= scale; a0 *= scale; a1 *= scale;
        float w = valid ? __expf(e - mnew) : 0.f;
        float ws = w;
#pragma unroll
        for (int o = 16; o; o >>= 1) ws += __shfl_xor_sync(FULLMASK, ws, o);
        ssum += ws;
        m = mnew;
        int cnt = min(32, end - base);
        for (int j = 0; j < cnt; j += 8) {          // invalid lanes carry w=0, s=0
            float wv[8]; float2 hv[8];
#pragma unroll
            for (int k = 0; k < 8; k++) {
                int sj = __shfl_sync(FULLMASK, s, j + k);
                wv[k] = __shfl_sync(FULLMASK, w, j + k);
                hv[k] = *reinterpret_cast<const float2*>(h + (size_t)sj * 64 + lane * 2);
            }
#pragma unroll
            for (int k = 0; k < 8; k++) { a0 += wv[k] * hv[k].x; a1 += wv[k] * hv[k].y; }
        }
    }
    float inv = 1.f / (ssum + 1e-16f);
    ro0 = a0 * inv;
    ro1 = a1 * inv;
}

// ---------------- K6: aggr layer1 (+bias+relu)  ||  scatter layer2 -----------
__global__ void aggr_scatter_kernel(const int* __restrict__ rowptr, const int* __restrict__ csr,
        const float* __restrict__ as_, const float* __restrict__ ad_,
        const float* __restrict__ h, const float* __restrict__ bias,
        float* __restrict__ aggout, int n, int warp_blocks,
        const int* __restrict__ src2, const int* __restrict__ dst2,
        int* __restrict__ cur2, int* __restrict__ csr2, int ne) {
    int b = blockIdx.x;
    if (b >= warp_blocks) {                 // scatter for layer 2
        b -= warp_blocks;
        int i = b * blockDim.x + threadIdx.x;
        if (i < ne) {
            int d = dst2[i];
            int p = atomicAdd(&cur2[d], 1);
            csr2[p] = src2[i];
        }
        return;
    }
    int gt = b * blockDim.x + threadIdx.x;
    int nd = gt >> 5;
    int lane = gt & 31;
    if (nd >= n) return;
    float o0, o1;
    aggr_core(rowptr, csr, as_, ad_, h, nd, lane, o0, o1);
    o0 = fmaxf(o0 + bias[lane * 2], 0.f);
    o1 = fmaxf(o1 + bias[lane * 2 + 1], 0.f);
    *reinterpret_cast<float2*>(aggout + (size_t)nd * 64 + lane * 2) = make_float2(o0, o1);
}

// ---------------- K7: gemm_score layer2 --------------------------------------
__global__ void gemm2_kernel(const float* __restrict__ X, const float* __restrict__ W,
        const float* __restrict__ att_s, const float* __restrict__ att_d,
        float* __restrict__ C, float* __restrict__ as_, float* __restrict__ ad_, int n) {
    gemm_score_body<HID>(blockIdx.x, X, W, att_s, att_d, C, as_, ad_, n);
}

// ---------------- K8: aggr layer2 + bias + linear + log_softmax --------------
__global__ void aggr_final_kernel(const int* __restrict__ rowptr, const int* __restrict__ csr,
        const float* __restrict__ as_, const float* __restrict__ ad_,
        const float* __restrict__ h, const float* __restrict__ bias,
        const float* __restrict__ Wlin, const float* __restrict__ blin,
        float* __restrict__ out, int n) {
    __shared__ float Ws[64 * 32];
    for (int i = threadIdx.x; i < 64 * 32; i += blockDim.x) Ws[i] = Wlin[i];
    __syncthreads();
    int gt = blockIdx.x * blockDim.x + threadIdx.x;
    int nd = gt >> 5;
    int lane = gt & 31;
    if (nd >= n) return;
    float o0, o1;
    aggr_core(rowptr, csr, as_, ad_, h, nd, lane, o0, o1);
    o0 += bias[lane * 2];
    o1 += bias[lane * 2 + 1];
    // y[c] = blin[c] + sum_k row[k] * Wlin[k][c], row[2j]=o0@lane j, row[2j+1]=o1@lane j
    float y = blin[lane];
#pragma unroll
    for (int j = 0; j < 32; j++) {
        float r0 = __shfl_sync(FULLMASK, o0, j);
        float r1 = __shfl_sync(FULLMASK, o1, j);
        y += r0 * Ws[(2 * j) * 32 + lane] + r1 * Ws[(2 * j + 1) * 32 + lane];
    }
    float m = y;
#pragma unroll
    for (int o = 16; o; o >>= 1) m = fmaxf(m, __shfl_xor_sync(FULLMASK, m, o));
    float ex = __expf(y - m);
    float ss = ex;
#pragma unroll
    for (int o = 16; o; o >>= 1) ss += __shfl_xor_sync(FULLMASK, ss, o);
    out[(size_t)nd * 32 + lane] = y - m - __logf(ss);
}

// ---------------- launch ------------------------------------------------------
extern "C" void kernel_launch(void* const* d_in, const int* in_sizes, int n_in,
                              void* d_out, int out_size) {
    const float* x        = (const float*)d_in[0];
    const int*   ei1      = (const int*)d_in[1];
    const int*   ei2      = (const int*)d_in[2];
    const float* W1       = (const float*)d_in[3];
    const float* att_src1 = (const float*)d_in[4];
    const float* att_dst1 = (const float*)d_in[5];
    const float* b1       = (const float*)d_in[6];
    const float* W2       = (const float*)d_in[7];
    const float* att_src2 = (const float*)d_in[8];
    const float* att_dst2 = (const float*)d_in[9];
    const float* b2       = (const float*)d_in[10];
    const float* Wlin     = (const float*)d_in[11];
    const float* blin     = (const float*)d_in[12];
    float* out = (float*)d_out;

    const int n = in_sizes[0] / FIN;       // 100000
    const int e = in_sizes[1] / 2;         // 1600000

    float *h, *agg, *as_, *ad_;
    int *deg1, *rp1, *cur1, *csr1, *bs1;
    int *deg2, *rp2, *cur2, *csr2, *bs2;
    cudaGetSymbolAddress((void**)&h,    g_h);
    cudaGetSymbolAddress((void**)&agg,  g_agg);
    cudaGetSymbolAddress((void**)&as_,  g_as);
    cudaGetSymbolAddress((void**)&ad_,  g_ad);
    cudaGetSymbolAddress((void**)&deg1, g_deg1);
    cudaGetSymbolAddress((void**)&rp1,  g_rp1);
    cudaGetSymbolAddress((void**)&cur1, g_cur1);
    cudaGetSymbolAddress((void**)&csr1, g_csr1);
    cudaGetSymbolAddress((void**)&bs1,  g_bsum1);
    cudaGetSymbolAddress((void**)&deg2, g_deg2);
    cudaGetSymbolAddress((void**)&rp2,  g_rp2);
    cudaGetSymbolAddress((void**)&cur2, g_cur2);
    cudaGetSymbolAddress((void**)&csr2, g_csr2);
    cudaGetSymbolAddress((void**)&bs2,  g_bsum2);

    const int TB = 256;
    int gemm_blocks = (n + 127) / 128;                   // 782
    int node_blocks = (n + TB - 1) / TB;                 // 391
    int warp_blocks = (n * 32 + TB - 1) / TB;            // 12500
    int eb          = (e + TB - 1) / TB;                 // 6250
    int hb          = (e + 4 * TB - 1) / (4 * TB);       // 1563
    int sb          = (n + SCAN_CHUNK - 1) / SCAN_CHUNK; // 98

    // K1: zero degree arrays
    zero2_kernel<<<node_blocks, TB>>>(deg1, deg2, n);
    // K2: gemm1+score1 || hist1 || hist2
    gemm1_hist_kernel<<<gemm_blocks + 2 * hb, TB>>>(
        x, W1, att_src1, att_dst1, h, as_, ad_, n, gemm_blocks,
        ei1 + e, deg1, ei2 + e, deg2, e, hb);
    // K3/K4: rowptr scans (both layers)
    scan_block2_kernel<<<2 * sb, TB>>>(deg1, deg2, rp1, rp2, bs1, bs2, n, sb);
    scan_add2_kernel<<<2 * node_blocks, TB>>>(rp1, cur1, bs1, rp2, cur2, bs2, n, e, node_blocks);
    // K5: scatter layer 1 (int4)
    scatter1_kernel<<<hb, TB>>>(ei1, ei1 + e, cur1, csr1, e);
    // K6: aggr layer1 (+bias+relu)  ||  scatter layer 2
    aggr_scatter_kernel<<<warp_blocks + eb, TB>>>(
        rp1, csr1, as_, ad_, h, b1, agg, n, warp_blocks,
        ei2, ei2 + e, cur2, csr2, e);
    // K7: gemm2+score2
    gemm2_kernel<<<gemm_blocks, TB>>>(agg, W2, att_src2, att_dst2, h, as_, ad_, n);
    // K8: aggr layer2 + linear + log_softmax
    aggr_final_kernel<<<warp_blocks, TB>>>(
        rp2, csr2, as_, ad_, h, b2, Wlin, blin, out, n);
}

// round 9
// speedup vs baseline: 1.5849x; 1.0898x over previous
#include <cuda_runtime.h>
#include <cuda_bf16.h>
#include <cuda_fp16.h>
#include <math_constants.h>

#define FIN 128
#define HID 64
#define NNODES 100000
#define NEDGES 1600000
#define SCAN_CHUNK 1024
#define FULLMASK 0xFFFFFFFFu

// ---------------- scratch (static device globals; no allocation) -------------
__device__ __align__(256) __half g_h[NNODES * HID];   // fp16 gather source
__device__ __align__(256) float g_agg[NNODES * HID];
__device__ __align__(256) float g_as[NNODES];
__device__ __align__(256) float g_ad[NNODES];
__device__ __align__(256) int g_deg1[NNODES],        g_deg2[NNODES];
__device__ __align__(256) int g_rp1[NNODES + 1],     g_rp2[NNODES + 1];
__device__ __align__(256) int g_cur1[NNODES],        g_cur2[NNODES];
__device__ __align__(256) int g_csr1[NEDGES],        g_csr2[NEDGES];
__device__ __align__(256) int g_bsum1[256],          g_bsum2[256];

// ---------------- GEMM + fused attention scores (device body) ----------------
// C[n,64] (fp16) = X[n,K] @ W[K,64]; tile 128x64, micro 8x4 per thread.
// Scores computed from fp32 accumulators (unchanged precision).
template <int K>
__device__ __forceinline__ void gemm_score_body(int bid,
        const float* __restrict__ X, const float* __restrict__ W,
        const float* __restrict__ att_s, const float* __restrict__ att_d,
        __half* __restrict__ C, float* __restrict__ as_, float* __restrict__ ad_,
        int n) {
    __shared__ float Xs[128][36];
    __shared__ float Ws[32][64];
    int tid = threadIdx.x;
    int tx = tid & 15;
    int ty = tid >> 4;
    int row0 = bid * 128;
    float acc[8][4] = {};
    for (int k0 = 0; k0 < K; k0 += 32) {
        for (int l = tid; l < 1024; l += 256) {
            int r = l >> 3, c4 = l & 7;
            int nd = row0 + r;
            float4 v = make_float4(0.f, 0.f, 0.f, 0.f);
            if (nd < n) v = *reinterpret_cast<const float4*>(X + (size_t)nd * K + k0 + c4 * 4);
            *reinterpret_cast<float4*>(&Xs[r][c4 * 4]) = v;
        }
        for (int l = tid; l < 512; l += 256) {
            int kk = l >> 4, c4 = l & 15;
            *reinterpret_cast<float4*>(&Ws[kk][c4 * 4]) =
                *reinterpret_cast<const float4*>(W + (size_t)(k0 + kk) * 64 + c4 * 4);
        }
        __syncthreads();
#pragma unroll
        for (int kk = 0; kk < 32; kk += 4) {
            float4 wv0 = *reinterpret_cast<float4*>(&Ws[kk + 0][tx * 4]);
            float4 wv1 = *reinterpret_cast<float4*>(&Ws[kk + 1][tx * 4]);
            float4 wv2 = *reinterpret_cast<float4*>(&Ws[kk + 2][tx * 4]);
            float4 wv3 = *reinterpret_cast<float4*>(&Ws[kk + 3][tx * 4]);
#pragma unroll
            for (int r = 0; r < 8; r++) {
                float4 xq = *reinterpret_cast<float4*>(&Xs[ty * 8 + r][kk]);
                acc[r][0] += xq.x * wv0.x; acc[r][1] += xq.x * wv0.y;
                acc[r][2] += xq.x * wv0.z; acc[r][3] += xq.x * wv0.w;
                acc[r][0] += xq.y * wv1.x; acc[r][1] += xq.y * wv1.y;
                acc[r][2] += xq.y * wv1.z; acc[r][3] += xq.y * wv1.w;
                acc[r][0] += xq.z * wv2.x; acc[r][1] += xq.z * wv2.y;
                acc[r][2] += xq.z * wv2.z; acc[r][3] += xq.z * wv2.w;
                acc[r][0] += xq.w * wv3.x; acc[r][1] += xq.w * wv3.y;
                acc[r][2] += xq.w * wv3.z; acc[r][3] += xq.w * wv3.w;
            }
        }
        __syncthreads();
    }
    float asv[4], adv[4];
#pragma unroll
    for (int c = 0; c < 4; c++) { asv[c] = att_s[tx * 4 + c]; adv[c] = att_d[tx * 4 + c]; }
#pragma unroll
    for (int r = 0; r < 8; r++) {
        int nd = row0 + ty * 8 + r;
        if (nd < n) {
            __half2 p0 = __floats2half2_rn(acc[r][0], acc[r][1]);
            __half2 p1 = __floats2half2_rn(acc[r][2], acc[r][3]);
            uint2 pk;
            pk.x = *reinterpret_cast<unsigned*>(&p0);
            pk.y = *reinterpret_cast<unsigned*>(&p1);
            *reinterpret_cast<uint2*>(C + (size_t)nd * 64 + tx * 4) = pk;
        }
        float ps = acc[r][0] * asv[0] + acc[r][1] * asv[1] + acc[r][2] * asv[2] + acc[r][3] * asv[3];
        float pd = acc[r][0] * adv[0] + acc[r][1] * adv[1] + acc[r][2] * adv[2] + acc[r][3] * adv[3];
#pragma unroll
        for (int o = 1; o < 16; o <<= 1) {
            ps += __shfl_xor_sync(FULLMASK, ps, o);
            pd += __shfl_xor_sync(FULLMASK, pd, o);
        }
        if (tx == 0 && nd < n) { as_[nd] = ps; ad_[nd] = pd; }
    }
}

// ---------------- K1: zero both degree arrays --------------------------------
__global__ void zero2_kernel(int* __restrict__ d1, int* __restrict__ d2, int n) {
    int i = blockIdx.x * blockDim.x + threadIdx.x;
    if (i < n) { d1[i] = 0; d2[i] = 0; }
}

// ---------------- K2: gemm_score layer1  ||  hist1  ||  hist2 ----------------
__global__ void gemm1_hist_kernel(const float* __restrict__ X, const float* __restrict__ W,
        const float* __restrict__ att_s, const float* __restrict__ att_d,
        __half* __restrict__ C, float* __restrict__ as_, float* __restrict__ ad_, int n,
        int gemm_blocks,
        const int* __restrict__ dst1, int* __restrict__ deg1,
        const int* __restrict__ dst2, int* __restrict__ deg2, int ne, int hb) {
    int bid = blockIdx.x;
    if (bid < gemm_blocks) {
        gemm_score_body<FIN>(bid, X, W, att_s, att_d, C, as_, ad_, n);
        return;
    }
    bid -= gemm_blocks;
    const int* dstp; int* deg;
    if (bid < hb) { dstp = dst1; deg = deg1; }
    else          { bid -= hb; dstp = dst2; deg = deg2; }
    int base = (bid * blockDim.x + threadIdx.x) * 4;
    if (base + 3 < ne) {
        int4 d4 = *reinterpret_cast<const int4*>(dstp + base);
        atomicAdd(&deg[d4.x], 1);
        atomicAdd(&deg[d4.y], 1);
        atomicAdd(&deg[d4.z], 1);
        atomicAdd(&deg[d4.w], 1);
    } else {
        for (int i = base; i < ne; i++) atomicAdd(&deg[dstp[i]], 1);
    }
}

// ---------------- K3: per-chunk scan of both degree arrays -------------------
__global__ void scan_block2_kernel(const int* __restrict__ deg1, const int* __restrict__ deg2,
                                   int* __restrict__ rp1, int* __restrict__ rp2,
                                   int* __restrict__ bs1, int* __restrict__ bs2,
                                   int n, int sb) {
    __shared__ int tsum[256];
    int b = blockIdx.x;
    const int* deg; int* rowptr; int* bsum;
    if (b < sb) { deg = deg1; rowptr = rp1; bsum = bs1; }
    else        { b -= sb; deg = deg2; rowptr = rp2; bsum = bs2; }
    int t = threadIdx.x;
    int base = b * SCAN_CHUNK + t * 4;
    int v[4]; int s = 0;
#pragma unroll
    for (int j = 0; j < 4; j++) { v[j] = (base + j < n) ? deg[base + j] : 0; s += v[j]; }
    tsum[t] = s;
    __syncthreads();
    int acc = s;
    for (int off = 1; off < 256; off <<= 1) {
        int x = (t >= off) ? tsum[t - off] : 0;
        __syncthreads();
        tsum[t] += x;
        __syncthreads();
    }
    int excl = tsum[t] - acc;
    if (t == 255) bsum[b] = tsum[255];
    int run = excl;
#pragma unroll
    for (int j = 0; j < 4; j++) {
        if (base + j < n) rowptr[base + j] = run;
        run += v[j];
    }
}

// ---------------- K4: add chunk prefixes, init cur ---------------------------
__global__ void scan_add2_kernel(int* __restrict__ rp1, int* __restrict__ cur1,
                                 const int* __restrict__ bs1,
                                 int* __restrict__ rp2, int* __restrict__ cur2,
                                 const int* __restrict__ bs2,
                                 int n, int e, int node_blocks) {
    __shared__ int red[256];
    int b = blockIdx.x;
    int* rowptr; int* cur; const int* bsum;
    if (b < node_blocks) { rowptr = rp1; cur = cur1; bsum = bs1; }
    else                 { b -= node_blocks; rowptr = rp2; cur = cur2; bsum = bs2; }
    int t = threadIdx.x;
    int c = b >> 2;
    red[t] = (t < c) ? bsum[t] : 0;
    __syncthreads();
    for (int off = 128; off; off >>= 1) {
        if (t < off) red[t] += red[t + off];
        __syncthreads();
    }
    int prefix = red[0];
    int i = b * 256 + t;
    if (i < n) {
        int v = rowptr[i] + prefix;
        rowptr[i] = v;
        cur[i] = v;
    }
    if (b == 0 && t == 0) rowptr[n] = e;
}

// ---------------- K5: scatter layer 1 (int4, 4 edges/thread) -----------------
__global__ void scatter1_kernel(const int* __restrict__ src, const int* __restrict__ dst,
                                int* __restrict__ cur, int* __restrict__ csr, int ne) {
    int base = (blockIdx.x * blockDim.x + threadIdx.x) * 4;
    if (base + 3 < ne) {
        int4 s4 = *reinterpret_cast<const int4*>(src + base);
        int4 d4 = *reinterpret_cast<const int4*>(dst + base);
        int p;
        p = atomicAdd(&cur[d4.x], 1); csr[p] = s4.x;
        p = atomicAdd(&cur[d4.y], 1); csr[p] = s4.y;
        p = atomicAdd(&cur[d4.z], 1); csr[p] = s4.z;
        p = atomicAdd(&cur[d4.w], 1); csr[p] = s4.w;
    } else {
        for (int i = base; i < ne; i++) {
            int p = atomicAdd(&cur[dst[i]], 1);
            csr[p] = src[i];
        }
    }
}

// ---------------- fused single-pass softmax + aggregation (flash-style) ------
// warp per dst node; online max with accumulator rescaling; h gathered as fp16.
__device__ __forceinline__ void aggr_core(const int* __restrict__ rowptr,
                                          const int* __restrict__ csr,
                                          const float* __restrict__ as_,
                                          const float* __restrict__ ad_,
                                          const __half2* __restrict__ h2v,
                                          int nd, int lane,
                                          float& ro0, float& ro1) {
    int start = rowptr[nd];
    int end = rowptr[nd + 1];
    float adv = ad_[nd];
    float m = -CUDART_INF_F;
    float ssum = 0.f;
    float a0 = 0.f, a1 = 0.f;
    for (int base = start; base < end; base += 32) {
        int i = base + lane;
        bool valid = (i < end);
        int s = valid ? csr[i] : 0;
        float e = -CUDART_INF_F;
        if (valid) {
            float v = as_[s] + adv;
            e = (v > 0.f) ? v : 0.2f * v;
        }
        float cm = e;
#pragma unroll
        for (int o = 16; o; o >>= 1) cm = fmaxf(cm, __shfl_xor_sync(FULLMASK, cm, o));
        float mnew = fmaxf(m, cm);
        float scale = __expf(m - mnew);
        ssum *= scale; a0 *= scale; a1 *= scale;
        float w = valid ? __expf(e - mnew) : 0.f;
        float ws = w;
#pragma unroll
        for (int o = 16; o; o >>= 1) ws += __shfl_xor_sync(FULLMASK, ws, o);
        ssum += ws;
        m = mnew;
        int cnt = min(32, end - base);
        for (int j = 0; j < cnt; j += 8) {          // invalid lanes carry w=0, s=0
            float wv[8]; __half2 hr[8];
#pragma unroll
            for (int k = 0; k < 8; k++) {
                int sj = __shfl_sync(FULLMASK, s, j + k);
                wv[k] = __shfl_sync(FULLMASK, w, j + k);
                hr[k] = h2v[(size_t)sj * 32 + lane];
            }
#pragma unroll
            for (int k = 0; k < 8; k++) {
                float2 hv = __half22float2(hr[k]);
                a0 += wv[k] * hv.x;
                a1 += wv[k] * hv.y;
            }
        }
    }
    float inv = 1.f / (ssum + 1e-16f);
    ro0 = a0 * inv;
    ro1 = a1 * inv;
}

// ---------------- K6: aggr layer1 (+bias+relu)  ||  scatter layer2 -----------
__global__ void aggr_scatter_kernel(const int* __restrict__ rowptr, const int* __restrict__ csr,
        const float* __restrict__ as_, const float* __restrict__ ad_,
        const __half2* __restrict__ h2v, const float* __restrict__ bias,
        float* __restrict__ aggout, int n, int warp_blocks,
        const int* __restrict__ src2, const int* __restrict__ dst2,
        int* __restrict__ cur2, int* __restrict__ csr2, int ne) {
    int b = blockIdx.x;
    if (b >= warp_blocks) {                 // scatter for layer 2
        b -= warp_blocks;
        int i = b * blockDim.x + threadIdx.x;
        if (i < ne) {
            int d = dst2[i];
            int p = atomicAdd(&cur2[d], 1);
            csr2[p] = src2[i];
        }
        return;
    }
    int gt = b * blockDim.x + threadIdx.x;
    int nd = gt >> 5;
    int lane = gt & 31;
    if (nd >= n) return;
    float o0, o1;
    aggr_core(rowptr, csr, as_, ad_, h2v, nd, lane, o0, o1);
    o0 = fmaxf(o0 + bias[lane * 2], 0.f);
    o1 = fmaxf(o1 + bias[lane * 2 + 1], 0.f);
    *reinterpret_cast<float2*>(aggout + (size_t)nd * 64 + lane * 2) = make_float2(o0, o1);
}

// ---------------- K7: gemm_score layer2 --------------------------------------
__global__ void gemm2_kernel(const float* __restrict__ X, const float* __restrict__ W,
        const float* __restrict__ att_s, const float* __restrict__ att_d,
        __half* __restrict__ C, float* __restrict__ as_, float* __restrict__ ad_, int n) {
    gemm_score_body<HID>(blockIdx.x, X, W, att_s, att_d, C, as_, ad_, n);
}

// ---------------- K8: aggr layer2 + bias + linear + log_softmax --------------
__global__ void aggr_final_kernel(const int* __restrict__ rowptr, const int* __restrict__ csr,
        const float* __restrict__ as_, const float* __restrict__ ad_,
        const __half2* __restrict__ h2v, const float* __restrict__ bias,
        const float* __restrict__ Wlin, const float* __restrict__ blin,
        float* __restrict__ out, int n) {
    __shared__ float Ws[64 * 32];
    for (int i = threadIdx.x; i < 64 * 32; i += blockDim.x) Ws[i] = Wlin[i];
    __syncthreads();
    int gt = blockIdx.x * blockDim.x + threadIdx.x;
    int nd = gt >> 5;
    int lane = gt & 31;
    if (nd >= n) return;
    float o0, o1;
    aggr_core(rowptr, csr, as_, ad_, h2v, nd, lane, o0, o1);
    o0 += bias[lane * 2];
    o1 += bias[lane * 2 + 1];
    // y[c] = blin[c] + sum_k row[k] * Wlin[k][c], row[2j]=o0@lane j, row[2j+1]=o1@lane j
    float y = blin[lane];
#pragma unroll
    for (int j = 0; j < 32; j++) {
        float r0 = __shfl_sync(FULLMASK, o0, j);
        float r1 = __shfl_sync(FULLMASK, o1, j);
        y += r0 * Ws[(2 * j) * 32 + lane] + r1 * Ws[(2 * j + 1) * 32 + lane];
    }
    float m = y;
#pragma unroll
    for (int o = 16; o; o >>= 1) m = fmaxf(m, __shfl_xor_sync(FULLMASK, m, o));
    float ex = __expf(y - m);
    float ss = ex;
#pragma unroll
    for (int o = 16; o; o >>= 1) ss += __shfl_xor_sync(FULLMASK, ss, o);
    out[(size_t)nd * 32 + lane] = y - m - __logf(ss);
}

// ---------------- launch ------------------------------------------------------
extern "C" void kernel_launch(void* const* d_in, const int* in_sizes, int n_in,
                              void* d_out, int out_size) {
    const float* x        = (const float*)d_in[0];
    const int*   ei1      = (const int*)d_in[1];
    const int*   ei2      = (const int*)d_in[2];
    const float* W1       = (const float*)d_in[3];
    const float* att_src1 = (const float*)d_in[4];
    const float* att_dst1 = (const float*)d_in[5];
    const float* b1       = (const float*)d_in[6];
    const float* W2       = (const float*)d_in[7];
    const float* att_src2 = (const float*)d_in[8];
    const float* att_dst2 = (const float*)d_in[9];
    const float* b2       = (const float*)d_in[10];
    const float* Wlin     = (const float*)d_in[11];
    const float* blin     = (const float*)d_in[12];
    float* out = (float*)d_out;

    const int n = in_sizes[0] / FIN;       // 100000
    const int e = in_sizes[1] / 2;         // 1600000

    __half* h;
    float *agg, *as_, *ad_;
    int *deg1, *rp1, *cur1, *csr1, *bs1;
    int *deg2, *rp2, *cur2, *csr2, *bs2;
    cudaGetSymbolAddress((void**)&h,    g_h);
    cudaGetSymbolAddress((void**)&agg,  g_agg);
    cudaGetSymbolAddress((void**)&as_,  g_as);
    cudaGetSymbolAddress((void**)&ad_,  g_ad);
    cudaGetSymbolAddress((void**)&deg1, g_deg1);
    cudaGetSymbolAddress((void**)&rp1,  g_rp1);
    cudaGetSymbolAddress((void**)&cur1, g_cur1);
    cudaGetSymbolAddress((void**)&csr1, g_csr1);
    cudaGetSymbolAddress((void**)&bs1,  g_bsum1);
    cudaGetSymbolAddress((void**)&deg2, g_deg2);
    cudaGetSymbolAddress((void**)&rp2,  g_rp2);
    cudaGetSymbolAddress((void**)&cur2, g_cur2);
    cudaGetSymbolAddress((void**)&csr2, g_csr2);
    cudaGetSymbolAddress((void**)&bs2,  g_bsum2);
    const __half2* h2v = (const __half2*)h;

    const int TB = 256;
    int gemm_blocks = (n + 127) / 128;                   // 782
    int node_blocks = (n + TB - 1) / TB;                 // 391
    int warp_blocks = (n * 32 + TB - 1) / TB;            // 12500
    int eb          = (e + TB - 1) / TB;                 // 6250
    int hb          = (e + 4 * TB - 1) / (4 * TB);       // 1563
    int sb          = (n + SCAN_CHUNK - 1) / SCAN_CHUNK; // 98

    // K1: zero degree arrays
    zero2_kernel<<<node_blocks, TB>>>(deg1, deg2, n);
    // K2: gemm1+score1 || hist1 || hist2
    gemm1_hist_kernel<<<gemm_blocks + 2 * hb, TB>>>(
        x, W1, att_src1, att_dst1, h, as_, ad_, n, gemm_blocks,
        ei1 + e, deg1, ei2 + e, deg2, e, hb);
    // K3/K4: rowptr scans (both layers)
    scan_block2_kernel<<<2 * sb, TB>>>(deg1, deg2, rp1, rp2, bs1, bs2, n, sb);
    scan_add2_kernel<<<2 * node_blocks, TB>>>(rp1, cur1, bs1, rp2, cur2, bs2, n, e, node_blocks);
    // K5: scatter layer 1 (int4)
    scatter1_kernel<<<hb, TB>>>(ei1, ei1 + e, cur1, csr1, e);
    // K6: aggr layer1 (+bias+relu)  ||  scatter layer 2
    aggr_scatter_kernel<<<warp_blocks + eb, TB>>>(
        rp1, csr1, as_, ad_, h2v, b1, agg, n, warp_blocks,
        ei2, ei2 + e, cur2, csr2, e);
    // K7: gemm2+score2
    gemm2_kernel<<<gemm_blocks, TB>>>(agg, W2, att_src2, att_dst2, h, as_, ad_, n);
    // K8: aggr layer2 + linear + log_softmax
    aggr_final_kernel<<<warp_blocks, TB>>>(
        rp2, csr2, as_, ad_, h2v, b2, Wlin, blin, out, n);
}